// round 6
// baseline (speedup 1.0000x reference)
#include <cuda_runtime.h>
#include <cuda_bf16.h>
#include <stdint.h>

// Problem constants
#define NE 16384   // edges
// features [E,32,16], basis [E,16,44,16], w3 [45056,32], out [E,32,16]

// Intermediate: radial MLP hidden output H[E,32]
__device__ float g_H[NE * 32];

// ---------------------------------------------------------------------------
// helpers
// ---------------------------------------------------------------------------
__device__ __forceinline__ uint32_t f2tf(float x) {
    uint32_t r;
    asm("cvt.rna.tf32.f32 %0, %1;" : "=r"(r) : "f"(x));
    return r;
}
__device__ __forceinline__ float f2tf_f(float x) {
    return __uint_as_float(f2tf(x));
}
__device__ __forceinline__ void mma8(float* d, const uint32_t* a, uint32_t b0, uint32_t b1) {
    asm volatile(
        "mma.sync.aligned.m16n8k8.row.col.f32.tf32.tf32.f32 "
        "{%0,%1,%2,%3}, {%4,%5,%6,%7}, {%8,%9}, {%0,%1,%2,%3};"
        : "+f"(d[0]), "+f"(d[1]), "+f"(d[2]), "+f"(d[3])
        : "r"(a[0]), "r"(a[1]), "r"(a[2]), "r"(a[3]), "r"(b0), "r"(b1));
}

// ---------------------------------------------------------------------------
// Kernel 1: radial MLP (Linear->LN->ReLU->Linear->LN->ReLU) -> g_H
// thread per edge, exact fp32
// ---------------------------------------------------------------------------
__global__ void mlp_kernel(const float* __restrict__ x,
                           const float* __restrict__ w1, const float* __restrict__ b1,
                           const float* __restrict__ g1, const float* __restrict__ be1,
                           const float* __restrict__ w2, const float* __restrict__ b2,
                           const float* __restrict__ g2, const float* __restrict__ be2) {
    int e = blockIdx.x * blockDim.x + threadIdx.x;
    if (e >= NE) return;

    float xin[16];
#pragma unroll
    for (int j = 0; j < 16; j++) xin[j] = x[e * 16 + j];

    float h1[32];
#pragma unroll
    for (int m = 0; m < 32; m++) {
        float s = b1[m];
#pragma unroll
        for (int j = 0; j < 16; j++) s = fmaf(xin[j], w1[m * 16 + j], s);
        h1[m] = s;
    }
    float mu = 0.f;
#pragma unroll
    for (int m = 0; m < 32; m++) mu += h1[m];
    mu *= (1.0f / 32.0f);
    float var = 0.f;
#pragma unroll
    for (int m = 0; m < 32; m++) { float d = h1[m] - mu; var = fmaf(d, d, var); }
    var *= (1.0f / 32.0f);
    float inv = rsqrtf(var + 1e-5f);
#pragma unroll
    for (int m = 0; m < 32; m++)
        h1[m] = fmaxf((h1[m] - mu) * inv * g1[m] + be1[m], 0.0f);

    float h2[32];
#pragma unroll
    for (int m = 0; m < 32; m++) {
        float s = b2[m];
#pragma unroll
        for (int j = 0; j < 32; j++) s = fmaf(h1[j], w2[m * 32 + j], s);
        h2[m] = s;
    }
    mu = 0.f;
#pragma unroll
    for (int m = 0; m < 32; m++) mu += h2[m];
    mu *= (1.0f / 32.0f);
    var = 0.f;
#pragma unroll
    for (int m = 0; m < 32; m++) { float d = h2[m] - mu; var = fmaf(d, d, var); }
    var *= (1.0f / 32.0f);
    inv = rsqrtf(var + 1e-5f);
#pragma unroll
    for (int m = 0; m < 32; m++)
        g_H[e * 32 + m] = fmaxf((h2[m] - mu) * inv * g2[m] + be2[m], 0.0f);
}

// ---------------------------------------------------------------------------
// Kernel 2: fused conv. CTA = 32 edges, 512 threads (16 warps), tf32 mma.
//
// smem layout (float offsets):
//   H_OFF   [32e][36]                 (H, pre-rounded to tf32)       1152
//   TMP_OFF [32e][16s][36 (ci)]       tmp_f in B-operand layout     18560
//   W3B_OFF [512r][36] / basis alias  w3 chunk OR basis_f           18432
//   RW_OFF  [32e][16co][36 (ci)]      radial weights chunk          18560
// total 56704 floats = 226816 bytes (opt-in)
// ---------------------------------------------------------------------------
#define H_OFF    0
#define TMP_OFF  1152
#define W3B_OFF  19712
#define RW_OFF   38144
#define SMEM_FLOATS 56704
#define SMEM_BYTES  (SMEM_FLOATS * 4)

__global__ void __launch_bounds__(512, 1)
conv_kernel(const float* __restrict__ feat,
            const float* __restrict__ basis,
            const float* __restrict__ w3,
            float* __restrict__ out) {
    extern __shared__ float sm[];
    const int t    = threadIdx.x;
    const int wid  = t >> 5;
    const int lane = t & 31;
    const int g    = lane >> 2;   // groupID (0..7)
    const int tg   = lane & 3;    // thread in group (0..3)
    const int b    = blockIdx.x;
    const int e0   = b * 32;      // first global edge of this CTA

    // ---- load H tile [32][32] -> H_OFF (stride 36), pre-rounded to tf32 ----
    {
        int e = t >> 4, m = (t & 15) * 2;
        const float* src = g_H + (size_t)(e0 + e) * 32 + m;
        sm[H_OFF + e * 36 + m]     = f2tf_f(src[0]);
        sm[H_OFF + e * 36 + m + 1] = f2tf_f(src[1]);
    }
    // ---- stage features through smem scratch (spans TMP..RW regions) ----
    // scratch layout: [e][r*20 + c] (conflict-free fragment reads)
    {
        const float4* src = reinterpret_cast<const float4*>(feat + (size_t)e0 * 512);
#pragma unroll
        for (int j = 0; j < 8; j++) {
            int idx = t + j * 512;
            int e = idx >> 7, pos = (idx & 127) * 4;
            int r = pos >> 4, c0 = pos & 15;
            float4 v = src[idx];
            float* d = sm + TMP_OFF + e * 640 + r * 20 + c0;
            d[0] = v.x; d[1] = v.y; d[2] = v.z; d[3] = v.w;
        }
    }
    __syncthreads();

    // ---- per-warp feature A-fragments (2 edges/warp), kept in regs ----
    uint32_t fa[2][2][2][4];   // [edge][mtile (ci half)][kstep][frag]
#pragma unroll
    for (int le = 0; le < 2; le++) {
        const float* fs = sm + TMP_OFF + (wid * 2 + le) * 640;
#pragma unroll
        for (int mt = 0; mt < 2; mt++)
#pragma unroll
            for (int k = 0; k < 2; k++) {
                int r = mt * 16 + g, c = k * 8 + tg;
                fa[le][mt][k][0] = f2tf(fs[r * 20 + c]);
                fa[le][mt][k][1] = f2tf(fs[(r + 8) * 20 + c]);
                fa[le][mt][k][2] = f2tf(fs[r * 20 + c + 4]);
                fa[le][mt][k][3] = f2tf(fs[(r + 8) * 20 + c + 4]);
            }
    }
    __syncthreads();   // scratch regions reused below

    // persistent output accumulators: [edge][co-chunk][s-ntile][frag]
    float acc[2][2][2][4];
#pragma unroll
    for (int a = 0; a < 2; a++)
#pragma unroll
        for (int c = 0; c < 2; c++)
#pragma unroll
            for (int n = 0; n < 2; n++)
#pragma unroll
                for (int r = 0; r < 4; r++) acc[a][c][n][r] = 0.f;

    for (int f = 0; f < 44; f++) {
        // ---- stage basis_f [32e][16i][16s] into W3B region (i-stride 24) ----
#pragma unroll
        for (int j = 0; j < 4; j++) {
            int idx = t + j * 512;
            int e = idx >> 6, rem = idx & 63;
            int i = rem >> 2, q = (rem & 3) * 4;
            const float4 v = *reinterpret_cast<const float4*>(
                basis + (size_t)(e0 + e) * 11264 + i * 704 + f * 16 + q);
            *reinterpret_cast<float4*>(sm + W3B_OFF + e * 384 + i * 24 + q) = v;
        }
        __syncthreads();

        // ---- GEMM2: tmp_f[e][ci][s] = feat_e @ basis_f_e ; store as [e][s][ci] ----
#pragma unroll
        for (int le = 0; le < 2; le++) {
            int e = wid * 2 + le;
            const float* bs = sm + W3B_OFF + e * 384;
            float* tp = sm + TMP_OFF + e * 580;
#pragma unroll
            for (int nt = 0; nt < 2; nt++) {
                uint32_t bb[2][2];
#pragma unroll
                for (int k = 0; k < 2; k++) {
                    bb[k][0] = f2tf(bs[(k * 8 + tg) * 24 + nt * 8 + g]);
                    bb[k][1] = f2tf(bs[(k * 8 + tg + 4) * 24 + nt * 8 + g]);
                }
#pragma unroll
                for (int mt = 0; mt < 2; mt++) {
                    float c4[4] = {0.f, 0.f, 0.f, 0.f};
                    mma8(c4, fa[le][mt][0], bb[0][0], bb[0][1]);
                    mma8(c4, fa[le][mt][1], bb[1][0], bb[1][1]);
                    int sA = nt * 8 + 2 * tg, ciA = mt * 16 + g;
                    tp[sA * 36 + ciA]           = c4[0];
                    tp[(sA + 1) * 36 + ciA]     = c4[1];
                    tp[sA * 36 + ciA + 8]       = c4[2];
                    tp[(sA + 1) * 36 + ciA + 8] = c4[3];
                }
            }
        }
        __syncthreads();

        // ---- co-chunk loop (co in [c*16, c*16+16)) ----
#pragma unroll
        for (int c = 0; c < 2; c++) {
            // stage w3 chunk: rows r = co_c*32+ci, global row (c*16+co_c)*1408 + ci*44 + f
#pragma unroll
            for (int j = 0; j < 8; j++) {
                int idx = t + j * 512;
                int r = idx >> 3, q = (idx & 7) * 4;
                int co = c * 16 + (r >> 5), ci = r & 31;
                const float4 v = *reinterpret_cast<const float4*>(
                    w3 + (size_t)(co * 1408 + ci * 44 + f) * 32 + q);
                *reinterpret_cast<float4*>(sm + W3B_OFF + r * 36 + q) = v;
            }
            __syncthreads();

            // GEMM1: RW[r=(co_c,ci)][e] = sum_m w3[r][m] * H[e][m]
            // warp wid owns rows [wid*32, wid*32+32)  (co_c = wid)
            {
                const float* W = sm + W3B_OFF + wid * 32 * 36;
#pragma unroll
                for (int mt = 0; mt < 2; mt++) {
                    float c16[4][4] = {{0.f,0.f,0.f,0.f},{0.f,0.f,0.f,0.f},
                                       {0.f,0.f,0.f,0.f},{0.f,0.f,0.f,0.f}};
#pragma unroll
                    for (int k = 0; k < 4; k++) {
                        const float* Wm = W + mt * 16 * 36;
                        uint32_t aa[4];
                        aa[0] = f2tf(Wm[g * 36 + k * 8 + tg]);
                        aa[1] = f2tf(Wm[(g + 8) * 36 + k * 8 + tg]);
                        aa[2] = f2tf(Wm[g * 36 + k * 8 + tg + 4]);
                        aa[3] = f2tf(Wm[(g + 8) * 36 + k * 8 + tg + 4]);
#pragma unroll
                        for (int nt = 0; nt < 4; nt++) {
                            // H pre-rounded to tf32: reinterpret directly
                            uint32_t b0 = __float_as_uint(sm[H_OFF + (nt * 8 + g) * 36 + k * 8 + tg]);
                            uint32_t b1 = __float_as_uint(sm[H_OFF + (nt * 8 + g) * 36 + k * 8 + tg + 4]);
                            mma8(c16[nt], aa, b0, b1);
                        }
                    }
                    // store RW[e][co_c=wid][ci]
#pragma unroll
                    for (int nt = 0; nt < 4; nt++) {
                        float* R = sm + RW_OFF + wid * 36;
                        int cib = mt * 16 + g;
                        int eb = nt * 8 + 2 * tg;
                        R[(size_t)eb * 580 + cib]           = c16[nt][0];
                        R[(size_t)(eb + 1) * 580 + cib]     = c16[nt][1];
                        R[(size_t)eb * 580 + cib + 8]       = c16[nt][2];
                        R[(size_t)(eb + 1) * 580 + cib + 8] = c16[nt][3];
                    }
                }
            }
            __syncthreads();

            // GEMM3: out_e[co16, s16] += RW_e[co16, ci32] @ tmp_e[ci32, s16]
#pragma unroll
            for (int le = 0; le < 2; le++) {
                int e = wid * 2 + le;
                const float* R = sm + RW_OFF + e * 580;
                const float* T = sm + TMP_OFF + e * 580;
#pragma unroll
                for (int k = 0; k < 4; k++) {
                    uint32_t aa[4];
                    aa[0] = f2tf(R[g * 36 + k * 8 + tg]);
                    aa[1] = f2tf(R[(g + 8) * 36 + k * 8 + tg]);
                    aa[2] = f2tf(R[g * 36 + k * 8 + tg + 4]);
                    aa[3] = f2tf(R[(g + 8) * 36 + k * 8 + tg + 4]);
#pragma unroll
                    for (int nt = 0; nt < 2; nt++) {
                        uint32_t b0 = f2tf(T[(nt * 8 + g) * 36 + k * 8 + tg]);
                        uint32_t b1 = f2tf(T[(nt * 8 + g) * 36 + k * 8 + tg + 4]);
                        mma8(acc[le][c][nt], aa, b0, b1);
                    }
                }
            }
            __syncthreads();
        }
    }

    // ---- epilogue: acc -> smem scratch [e][co*16+s] (stride 516) -> coalesced gmem ----
#pragma unroll
    for (int le = 0; le < 2; le++) {
        int e = wid * 2 + le;
        float* o = sm + TMP_OFF + e * 516;
#pragma unroll
        for (int c = 0; c < 2; c++)
#pragma unroll
            for (int nt = 0; nt < 2; nt++) {
                int co = c * 16 + g, s = nt * 8 + 2 * tg;
                o[co * 16 + s]           = acc[le][c][nt][0];
                o[co * 16 + s + 1]       = acc[le][c][nt][1];
                o[(co + 8) * 16 + s]     = acc[le][c][nt][2];
                o[(co + 8) * 16 + s + 1] = acc[le][c][nt][3];
            }
    }
    __syncthreads();
    {
        float4* dst = reinterpret_cast<float4*>(out + (size_t)e0 * 512);
#pragma unroll
        for (int j = 0; j < 8; j++) {
            int idx = t + j * 512;
            int e = idx >> 7, pos = (idx & 127) * 4;
            const float* s4 = sm + TMP_OFF + e * 516 + pos;
            dst[idx] = make_float4(s4[0], s4[1], s4[2], s4[3]);
        }
    }
}

// ---------------------------------------------------------------------------
// launch
// ---------------------------------------------------------------------------
extern "C" void kernel_launch(void* const* d_in, const int* in_sizes, int n_in,
                              void* d_out, int out_size) {
    (void)in_sizes; (void)n_in; (void)out_size;
    const float* features = (const float*)d_in[0];
    const float* edge     = (const float*)d_in[1];
    const float* basis    = (const float*)d_in[2];
    const float* w1  = (const float*)d_in[3];
    const float* b1  = (const float*)d_in[4];
    const float* g1  = (const float*)d_in[5];
    const float* be1 = (const float*)d_in[6];
    const float* w2  = (const float*)d_in[7];
    const float* b2  = (const float*)d_in[8];
    const float* g2  = (const float*)d_in[9];
    const float* be2 = (const float*)d_in[10];
    const float* w3  = (const float*)d_in[11];
    float* out = (float*)d_out;

    cudaFuncSetAttribute(conv_kernel, cudaFuncAttributeMaxDynamicSharedMemorySize, SMEM_BYTES);

    mlp_kernel<<<NE / 256, 256>>>(edge, w1, b1, g1, be1, w2, b2, g2, be2);
    conv_kernel<<<NE / 32, 512, SMEM_BYTES>>>(features, basis, w3, out);
}

// round 10
// speedup vs baseline: 1.0881x; 1.0881x over previous
#include <cuda_runtime.h>
#include <cuda_bf16.h>
#include <stdint.h>

// Problem constants
#define NE 16384   // edges
// features [E,32,16], basis [E,16,44,16], w3 [45056,32], out [E,32,16]

// Intermediates
__device__ float g_H[NE * 32];            // radial MLP output, pre-rounded to tf32
__device__ float g_w3t[45056 * 32];       // w3 pre-rounded to tf32, blocked [f][c][r=co_l*32+ci][m]

// ---------------------------------------------------------------------------
// helpers
// ---------------------------------------------------------------------------
__device__ __forceinline__ uint32_t f2tf(float x) {
    uint32_t r;
    asm("cvt.rna.tf32.f32 %0, %1;" : "=r"(r) : "f"(x));
    return r;
}
__device__ __forceinline__ float f2tf_f(float x) {
    return __uint_as_float(f2tf(x));
}
__device__ __forceinline__ void mma8(float* d, const uint32_t* a, uint32_t b0, uint32_t b1) {
    asm volatile(
        "mma.sync.aligned.m16n8k8.row.col.f32.tf32.tf32.f32 "
        "{%0,%1,%2,%3}, {%4,%5,%6,%7}, {%8,%9}, {%0,%1,%2,%3};"
        : "+f"(d[0]), "+f"(d[1]), "+f"(d[2]), "+f"(d[3])
        : "r"(a[0]), "r"(a[1]), "r"(a[2]), "r"(a[3]), "r"(b0), "r"(b1));
}

// ---------------------------------------------------------------------------
// Kernel 0: pre-round w3 to tf32 into blocked layout
//   g_w3t[((f*2 + c)*512 + r)*32 + m],  r = co_local*32 + ci, co = c*16 + co_local
// ---------------------------------------------------------------------------
__global__ void w3t_kernel(const float* __restrict__ w3) {
    int idx = blockIdx.x * 256 + threadIdx.x;   // 45056*32 = 1441792 total
    int m  = idx & 31;
    int r  = (idx >> 5) & 511;
    int fc = idx >> 14;          // 0..87
    int f  = fc >> 1, c = fc & 1;
    int co = c * 16 + (r >> 5);
    int ci = r & 31;
    g_w3t[idx] = f2tf_f(__ldg(&w3[(size_t)(co * 1408 + ci * 44 + f) * 32 + m]));
}

// ---------------------------------------------------------------------------
// Kernel 1: radial MLP (Linear->LN->ReLU->Linear->LN->ReLU) -> g_H (tf32-rounded)
// ---------------------------------------------------------------------------
__global__ void mlp_kernel(const float* __restrict__ x,
                           const float* __restrict__ w1, const float* __restrict__ b1,
                           const float* __restrict__ g1, const float* __restrict__ be1,
                           const float* __restrict__ w2, const float* __restrict__ b2,
                           const float* __restrict__ g2, const float* __restrict__ be2) {
    int e = blockIdx.x * blockDim.x + threadIdx.x;
    if (e >= NE) return;

    float xin[16];
#pragma unroll
    for (int j = 0; j < 16; j++) xin[j] = x[e * 16 + j];

    float h1[32];
#pragma unroll
    for (int m = 0; m < 32; m++) {
        float s = b1[m];
#pragma unroll
        for (int j = 0; j < 16; j++) s = fmaf(xin[j], w1[m * 16 + j], s);
        h1[m] = s;
    }
    float mu = 0.f;
#pragma unroll
    for (int m = 0; m < 32; m++) mu += h1[m];
    mu *= (1.0f / 32.0f);
    float var = 0.f;
#pragma unroll
    for (int m = 0; m < 32; m++) { float d = h1[m] - mu; var = fmaf(d, d, var); }
    var *= (1.0f / 32.0f);
    float inv = rsqrtf(var + 1e-5f);
#pragma unroll
    for (int m = 0; m < 32; m++)
        h1[m] = fmaxf((h1[m] - mu) * inv * g1[m] + be1[m], 0.0f);

    float h2[32];
#pragma unroll
    for (int m = 0; m < 32; m++) {
        float s = b2[m];
#pragma unroll
        for (int j = 0; j < 32; j++) s = fmaf(h1[j], w2[m * 32 + j], s);
        h2[m] = s;
    }
    mu = 0.f;
#pragma unroll
    for (int m = 0; m < 32; m++) mu += h2[m];
    mu *= (1.0f / 32.0f);
    var = 0.f;
#pragma unroll
    for (int m = 0; m < 32; m++) { float d = h2[m] - mu; var = fmaf(d, d, var); }
    var *= (1.0f / 32.0f);
    inv = rsqrtf(var + 1e-5f);
#pragma unroll
    for (int m = 0; m < 32; m++)
        g_H[e * 32 + m] = f2tf_f(fmaxf((h2[m] - mu) * inv * g2[m] + be2[m], 0.0f));
}

// ---------------------------------------------------------------------------
// Kernel 2: fused conv. CTA = 32 edges, 512 threads (16 warps), tf32 mma.
//
// smem (floats):
//   TMP [32e][16s][36ci]  @ 0      18560   (tmp, warp-private per edge; also
//                                           prologue feat scratch / epilogue scratch)
//   RW0 [32e][16co][36ci] @ 18560  18560   (radial-weight chunk, buf c=0)
//   RW1                   @ 37120  18560   (buf c=1)
// total 55680 floats = 222720 B
// 2 __syncthreads per frequency iteration + 1 guarding the epilogue scratch.
// ---------------------------------------------------------------------------
#define TMP_OFF 0
#define RW_OFF  18560
#define RWSZ    18560
#define SMEM_BYTES (55680 * 4)

__global__ void __launch_bounds__(512, 1)
conv_kernel(const float* __restrict__ feat,
            const float* __restrict__ basis,
            float* __restrict__ out) {
    extern __shared__ float sm[];
    const int t    = threadIdx.x;
    const int wid  = t >> 5;
    const int lane = t & 31;
    const int g    = lane >> 2;   // 0..7
    const int tg   = lane & 3;    // 0..3
    const int e0   = blockIdx.x * 32;

    // ---- hoist H B-fragments (invariant over f and c): 32 regs ----
    uint32_t hB[4][4][2];
#pragma unroll
    for (int k = 0; k < 4; k++)
#pragma unroll
        for (int nt = 0; nt < 4; nt++) {
            hB[k][nt][0] = __float_as_uint(g_H[(size_t)(e0 + nt * 8 + g) * 32 + k * 8 + tg]);
            hB[k][nt][1] = __float_as_uint(g_H[(size_t)(e0 + nt * 8 + g) * 32 + k * 8 + tg + 4]);
        }

    // ---- stage features -> smem scratch (str-20 rows, conflict-free) ----
    {
        const float4* src = reinterpret_cast<const float4*>(feat + (size_t)e0 * 512);
#pragma unroll
        for (int j = 0; j < 8; j++) {
            int idx = t + j * 512;
            int e = idx >> 7, pos = (idx & 127) * 4;
            int r = pos >> 4, c0 = pos & 15;
            float4 v = src[idx];
            float* d = sm + e * 640 + r * 20 + c0;
            d[0] = v.x; d[1] = v.y; d[2] = v.z; d[3] = v.w;
        }
    }
    __syncthreads();

    // ---- hoist feature A-fragments (2 edges/warp): 32 regs ----
    uint32_t fa[2][2][2][4];   // [edge][mtile][kstep][frag]
#pragma unroll
    for (int le = 0; le < 2; le++) {
        const float* fs = sm + (wid * 2 + le) * 640;
#pragma unroll
        for (int mt = 0; mt < 2; mt++)
#pragma unroll
            for (int k = 0; k < 2; k++) {
                int r = mt * 16 + g, c = k * 8 + tg;
                fa[le][mt][k][0] = f2tf(fs[r * 20 + c]);
                fa[le][mt][k][1] = f2tf(fs[(r + 8) * 20 + c]);
                fa[le][mt][k][2] = f2tf(fs[r * 20 + c + 4]);
                fa[le][mt][k][3] = f2tf(fs[(r + 8) * 20 + c + 4]);
            }
    }
    __syncthreads();   // scratch regions reused below

    // output accumulators: [edge][co-chunk][s-ntile][frag]
    float acc[2][2][2][4];
#pragma unroll
    for (int a = 0; a < 2; a++)
#pragma unroll
        for (int c = 0; c < 2; c++)
#pragma unroll
            for (int n = 0; n < 2; n++)
#pragma unroll
                for (int r = 0; r < 4; r++) acc[a][c][n][r] = 0.f;

#pragma unroll 1
    for (int f = 0; f < 44; f++) {
        // ---- GEMM2: tmp_f[e] = feat_e @ basis_f_e  (basis direct from gmem) ----
#pragma unroll
        for (int le = 0; le < 2; le++) {
            int e = wid * 2 + le;
            const float* bb = basis + (size_t)(e0 + e) * 11264 + f * 16;
            float braw[8];
#pragma unroll
            for (int nt = 0; nt < 2; nt++)
#pragma unroll
                for (int k = 0; k < 2; k++) {
                    braw[nt * 4 + k * 2]     = __ldg(&bb[(k * 8 + tg) * 704 + nt * 8 + g]);
                    braw[nt * 4 + k * 2 + 1] = __ldg(&bb[(k * 8 + tg + 4) * 704 + nt * 8 + g]);
                }
            float* tp = sm + TMP_OFF + e * 580;
#pragma unroll
            for (int nt = 0; nt < 2; nt++) {
                uint32_t b00 = f2tf(braw[nt * 4 + 0]), b01 = f2tf(braw[nt * 4 + 1]);
                uint32_t b10 = f2tf(braw[nt * 4 + 2]), b11 = f2tf(braw[nt * 4 + 3]);
#pragma unroll
                for (int mt = 0; mt < 2; mt++) {
                    float c4[4] = {0.f, 0.f, 0.f, 0.f};
                    mma8(c4, fa[le][mt][0], b00, b01);
                    mma8(c4, fa[le][mt][1], b10, b11);
                    int sA = nt * 8 + 2 * tg, ciA = mt * 16 + g;
                    tp[sA * 36 + ciA]           = f2tf_f(c4[0]);
                    tp[(sA + 1) * 36 + ciA]     = f2tf_f(c4[1]);
                    tp[sA * 36 + ciA + 8]       = f2tf_f(c4[2]);
                    tp[(sA + 1) * 36 + ciA + 8] = f2tf_f(c4[3]);
                }
            }
        }

#pragma unroll
        for (int c = 0; c < 2; c++) {
            // ---- GEMM1: RW[co_l=wid][ci][e] from w3t (direct L2 LDG) x hB regs ----
            const float* wb = g_w3t + ((size_t)(f * 2 + c) * 512 + wid * 32) * 32;
            float* Rw = sm + RW_OFF + c * RWSZ + wid * 36;
#pragma unroll
            for (int mt = 0; mt < 2; mt++) {
                const float* W = wb + mt * 16 * 32;
                uint32_t ar[16];
#pragma unroll
                for (int k = 0; k < 4; k++) {
                    ar[k * 4 + 0] = __float_as_uint(__ldg(&W[g * 32 + k * 8 + tg]));
                    ar[k * 4 + 1] = __float_as_uint(__ldg(&W[(g + 8) * 32 + k * 8 + tg]));
                    ar[k * 4 + 2] = __float_as_uint(__ldg(&W[g * 32 + k * 8 + tg + 4]));
                    ar[k * 4 + 3] = __float_as_uint(__ldg(&W[(g + 8) * 32 + k * 8 + tg + 4]));
                }
#pragma unroll
                for (int nt = 0; nt < 4; nt++) {
                    float c4[4] = {0.f, 0.f, 0.f, 0.f};
#pragma unroll
                    for (int k = 0; k < 4; k++)
                        mma8(c4, &ar[k * 4], hB[k][nt][0], hB[k][nt][1]);
                    int eb = nt * 8 + 2 * tg;
                    Rw[eb * 580 + mt * 16 + g]           = f2tf_f(c4[0]);
                    Rw[(eb + 1) * 580 + mt * 16 + g]     = f2tf_f(c4[1]);
                    Rw[eb * 580 + mt * 16 + g + 8]       = f2tf_f(c4[2]);
                    Rw[(eb + 1) * 580 + mt * 16 + g + 8] = f2tf_f(c4[3]);
                }
            }
            __syncthreads();

            // ---- GEMM3: out_e[co16,s16] += RW_e[co16,ci32] @ tmp_e[ci32,s16] ----
#pragma unroll
            for (int le = 0; le < 2; le++) {
                int e = wid * 2 + le;
                const float* R = sm + RW_OFF + c * RWSZ + e * 580;
                const float* T = sm + TMP_OFF + e * 580;
#pragma unroll
                for (int k = 0; k < 4; k++) {
                    uint32_t aa[4];
                    aa[0] = __float_as_uint(R[g * 36 + k * 8 + tg]);
                    aa[1] = __float_as_uint(R[(g + 8) * 36 + k * 8 + tg]);
                    aa[2] = __float_as_uint(R[g * 36 + k * 8 + tg + 4]);
                    aa[3] = __float_as_uint(R[(g + 8) * 36 + k * 8 + tg + 4]);
#pragma unroll
                    for (int nt = 0; nt < 2; nt++) {
                        uint32_t b0 = __float_as_uint(T[(nt * 8 + g) * 36 + k * 8 + tg]);
                        uint32_t b1 = __float_as_uint(T[(nt * 8 + g) * 36 + k * 8 + tg + 4]);
                        mma8(acc[le][c][nt], aa, b0, b1);
                    }
                }
            }
        }
    }

    // ---- BARRIER: all warps must finish their final GEMM3 TMP/RW reads before
    //      the epilogue scratch (stride 516, overlapping other warps' TMP rows)
    //      is written. This missing sync was the R8 correctness bug. ----
    __syncthreads();

    // ---- epilogue: acc -> smem scratch [e][co*16+s] (stride 516) -> coalesced gmem ----
#pragma unroll
    for (int le = 0; le < 2; le++) {
        float* o = sm + (wid * 2 + le) * 516;
#pragma unroll
        for (int c = 0; c < 2; c++)
#pragma unroll
            for (int nt = 0; nt < 2; nt++) {
                int co = c * 16 + g, s = nt * 8 + 2 * tg;
                o[co * 16 + s]           = acc[le][c][nt][0];
                o[co * 16 + s + 1]       = acc[le][c][nt][1];
                o[(co + 8) * 16 + s]     = acc[le][c][nt][2];
                o[(co + 8) * 16 + s + 1] = acc[le][c][nt][3];
            }
    }
    __syncthreads();
    {
        float4* dst = reinterpret_cast<float4*>(out + (size_t)e0 * 512);
#pragma unroll
        for (int j = 0; j < 8; j++) {
            int idx = t + j * 512;
            int e = idx >> 7, pos = (idx & 127) * 4;
            const float* s4 = sm + e * 516 + pos;
            dst[idx] = make_float4(s4[0], s4[1], s4[2], s4[3]);
        }
    }
}

// ---------------------------------------------------------------------------
// launch
// ---------------------------------------------------------------------------
extern "C" void kernel_launch(void* const* d_in, const int* in_sizes, int n_in,
                              void* d_out, int out_size) {
    (void)in_sizes; (void)n_in; (void)out_size;
    const float* features = (const float*)d_in[0];
    const float* edge     = (const float*)d_in[1];
    const float* basis    = (const float*)d_in[2];
    const float* w1  = (const float*)d_in[3];
    const float* b1  = (const float*)d_in[4];
    const float* g1  = (const float*)d_in[5];
    const float* be1 = (const float*)d_in[6];
    const float* w2  = (const float*)d_in[7];
    const float* b2  = (const float*)d_in[8];
    const float* g2  = (const float*)d_in[9];
    const float* be2 = (const float*)d_in[10];
    const float* w3  = (const float*)d_in[11];
    float* out = (float*)d_out;

    cudaFuncSetAttribute(conv_kernel, cudaFuncAttributeMaxDynamicSharedMemorySize, SMEM_BYTES);

    w3t_kernel<<<45056 * 32 / 256, 256>>>(w3);
    mlp_kernel<<<NE / 256, 256>>>(edge, w1, b1, g1, be1, w2, b2, g2, be2);
    conv_kernel<<<NE / 32, 512, SMEM_BYTES>>>(features, basis, out);
}

// round 12
// speedup vs baseline: 1.5514x; 1.4258x over previous
#include <cuda_runtime.h>
#include <cuda_bf16.h>
#include <stdint.h>

// Problem constants
#define NE 16384   // edges
// features [E,32,16], basis [E,16,44,16], w3 [45056,32], out [E,32,16]

// Intermediates
__device__ float g_H[NE * 32];        // radial MLP output, pre-rounded to tf32
// w3 pre-rounded to tf32, FRAGMENT-CONTIGUOUS layout:
//   idx = (((fc*16 + wid)*2 + mt)*4 + q)*128 + lane*4 + v
//   (fc = f*2+c; warp wid owns co = c*16+wid; ci = mt*16 + (v&1 ? g+8 : g);
//    m = q*8 + tg + (v&2 ? 4 : 0))
__device__ float g_w3p[45056 * 32];

// ---------------------------------------------------------------------------
// helpers
// ---------------------------------------------------------------------------
__device__ __forceinline__ uint32_t f2tf(float x) {
    uint32_t r;
    asm("cvt.rna.tf32.f32 %0, %1;" : "=r"(r) : "f"(x));
    return r;
}
__device__ __forceinline__ float f2tf_f(float x) {
    return __uint_as_float(f2tf(x));
}
__device__ __forceinline__ void mma8(float* d, const uint32_t* a, uint32_t b0, uint32_t b1) {
    asm volatile(
        "mma.sync.aligned.m16n8k8.row.col.f32.tf32.tf32.f32 "
        "{%0,%1,%2,%3}, {%4,%5,%6,%7}, {%8,%9}, {%0,%1,%2,%3};"
        : "+f"(d[0]), "+f"(d[1]), "+f"(d[2]), "+f"(d[3])
        : "r"(a[0]), "r"(a[1]), "r"(a[2]), "r"(a[3]), "r"(b0), "r"(b1));
}

// ---------------------------------------------------------------------------
// Kernel 0: pre-round w3 to tf32 into the fragment-contiguous layout above.
// ---------------------------------------------------------------------------
__global__ void w3p_kernel(const float* __restrict__ w3) {
    int idx  = blockIdx.x * 256 + threadIdx.x;   // 45056*32 = 1441792 total
    int v    = idx & 3;
    int lane = (idx >> 2) & 31;
    int q    = (idx >> 7) & 3;
    int mt   = (idx >> 9) & 1;
    int wid  = (idx >> 10) & 15;
    int fc   = idx >> 14;          // 0..87
    int f = fc >> 1, c = fc & 1;
    int g = lane >> 2, tg = lane & 3;
    int ci = mt * 16 + ((v & 1) ? g + 8 : g);
    int m  = q * 8 + tg + ((v & 2) ? 4 : 0);
    int co = c * 16 + wid;
    g_w3p[idx] = f2tf_f(__ldg(&w3[(size_t)(co * 1408 + ci * 44 + f) * 32 + m]));
}

// ---------------------------------------------------------------------------
// Kernel 1: radial MLP (Linear->LN->ReLU->Linear->LN->ReLU) -> g_H (tf32-rounded)
// ---------------------------------------------------------------------------
__global__ void mlp_kernel(const float* __restrict__ x,
                           const float* __restrict__ w1, const float* __restrict__ b1,
                           const float* __restrict__ g1, const float* __restrict__ be1,
                           const float* __restrict__ w2, const float* __restrict__ b2,
                           const float* __restrict__ g2, const float* __restrict__ be2) {
    int e = blockIdx.x * blockDim.x + threadIdx.x;
    if (e >= NE) return;

    float xin[16];
#pragma unroll
    for (int j = 0; j < 16; j++) xin[j] = x[e * 16 + j];

    float h1[32];
#pragma unroll
    for (int m = 0; m < 32; m++) {
        float s = b1[m];
#pragma unroll
        for (int j = 0; j < 16; j++) s = fmaf(xin[j], w1[m * 16 + j], s);
        h1[m] = s;
    }
    float mu = 0.f;
#pragma unroll
    for (int m = 0; m < 32; m++) mu += h1[m];
    mu *= (1.0f / 32.0f);
    float var = 0.f;
#pragma unroll
    for (int m = 0; m < 32; m++) { float d = h1[m] - mu; var = fmaf(d, d, var); }
    var *= (1.0f / 32.0f);
    float inv = rsqrtf(var + 1e-5f);
#pragma unroll
    for (int m = 0; m < 32; m++)
        h1[m] = fmaxf((h1[m] - mu) * inv * g1[m] + be1[m], 0.0f);

    float h2[32];
#pragma unroll
    for (int m = 0; m < 32; m++) {
        float s = b2[m];
#pragma unroll
        for (int j = 0; j < 32; j++) s = fmaf(h1[j], w2[m * 32 + j], s);
        h2[m] = s;
    }
    mu = 0.f;
#pragma unroll
    for (int m = 0; m < 32; m++) mu += h2[m];
    mu *= (1.0f / 32.0f);
    var = 0.f;
#pragma unroll
    for (int m = 0; m < 32; m++) { float d = h2[m] - mu; var = fmaf(d, d, var); }
    var *= (1.0f / 32.0f);
    inv = rsqrtf(var + 1e-5f);
#pragma unroll
    for (int m = 0; m < 32; m++)
        g_H[e * 32 + m] = f2tf_f(fmaxf((h2[m] - mu) * inv * g2[m] + be2[m], 0.0f));
}

// ---------------------------------------------------------------------------
// Kernel 2: fused conv. CTA = 32 edges, 512 threads (16 warps), tf32 mma.
//
// smem (floats):
//   TMP [32e][16s][36ci]  @ 0      18560   (tmp, warp-private per edge; also
//                                           prologue feat scratch / epilogue scratch)
//   RW0 [32e][16co][36ci] @ 18560  18560   (radial-weight chunk, buf c=0)
//   RW1                   @ 37120  18560   (buf c=1)
// total 55680 floats = 222720 B
// 2 __syncthreads per frequency iteration + 1 guarding the epilogue scratch.
// ---------------------------------------------------------------------------
#define TMP_OFF 0
#define RW_OFF  18560
#define RWSZ    18560
#define SMEM_BYTES (55680 * 4)

__global__ void __launch_bounds__(512, 1)
conv_kernel(const float* __restrict__ feat,
            const float* __restrict__ basis,
            float* __restrict__ out) {
    extern __shared__ float sm[];
    const int t    = threadIdx.x;
    const int wid  = t >> 5;
    const int lane = t & 31;
    const int g    = lane >> 2;   // 0..7
    const int tg   = lane & 3;    // 0..3
    const int e0   = blockIdx.x * 32;

    // ---- hoist H B-fragments (invariant over f and c): 32 regs ----
    uint32_t hB[4][4][2];
#pragma unroll
    for (int k = 0; k < 4; k++)
#pragma unroll
        for (int nt = 0; nt < 4; nt++) {
            hB[k][nt][0] = __float_as_uint(g_H[(size_t)(e0 + nt * 8 + g) * 32 + k * 8 + tg]);
            hB[k][nt][1] = __float_as_uint(g_H[(size_t)(e0 + nt * 8 + g) * 32 + k * 8 + tg + 4]);
        }

    // ---- stage features -> smem scratch (str-20 rows, conflict-free) ----
    {
        const float4* src = reinterpret_cast<const float4*>(feat + (size_t)e0 * 512);
#pragma unroll
        for (int j = 0; j < 8; j++) {
            int idx = t + j * 512;
            int e = idx >> 7, pos = (idx & 127) * 4;
            int r = pos >> 4, c0 = pos & 15;
            float4 v = src[idx];
            float* d = sm + e * 640 + r * 20 + c0;
            d[0] = v.x; d[1] = v.y; d[2] = v.z; d[3] = v.w;
        }
    }
    __syncthreads();

    // ---- hoist feature A-fragments (2 edges/warp): 32 regs ----
    uint32_t fa[2][2][2][4];   // [edge][mtile][kstep][frag]
#pragma unroll
    for (int le = 0; le < 2; le++) {
        const float* fs = sm + (wid * 2 + le) * 640;
#pragma unroll
        for (int mt = 0; mt < 2; mt++)
#pragma unroll
            for (int k = 0; k < 2; k++) {
                int r = mt * 16 + g, c = k * 8 + tg;
                fa[le][mt][k][0] = f2tf(fs[r * 20 + c]);
                fa[le][mt][k][1] = f2tf(fs[(r + 8) * 20 + c]);
                fa[le][mt][k][2] = f2tf(fs[r * 20 + c + 4]);
                fa[le][mt][k][3] = f2tf(fs[(r + 8) * 20 + c + 4]);
            }
    }
    __syncthreads();   // scratch regions reused below

    // output accumulators: [edge][co-chunk][s-ntile][frag]
    float acc[2][2][2][4];
#pragma unroll
    for (int a = 0; a < 2; a++)
#pragma unroll
        for (int c = 0; c < 2; c++)
#pragma unroll
            for (int n = 0; n < 2; n++)
#pragma unroll
                for (int r = 0; r < 4; r++) acc[a][c][n][r] = 0.f;

#pragma unroll 1
    for (int f = 0; f < 44; f++) {
        // ---- GEMM2: tmp_f[e] = feat_e @ basis_f_e ----
        // Issue ALL basis loads (both edges) before any mma: single exposed
        // DRAM-latency window per f instead of two.
        float br[2][8];
#pragma unroll
        for (int le = 0; le < 2; le++) {
            const float* bb = basis + (size_t)(e0 + wid * 2 + le) * 11264 + f * 16;
#pragma unroll
            for (int nt = 0; nt < 2; nt++)
#pragma unroll
                for (int k = 0; k < 2; k++) {
                    br[le][nt * 4 + k * 2]     = __ldg(&bb[(k * 8 + tg) * 704 + nt * 8 + g]);
                    br[le][nt * 4 + k * 2 + 1] = __ldg(&bb[(k * 8 + tg + 4) * 704 + nt * 8 + g]);
                }
        }
#pragma unroll
        for (int le = 0; le < 2; le++) {
            float* tp = sm + TMP_OFF + (wid * 2 + le) * 580;
#pragma unroll
            for (int nt = 0; nt < 2; nt++) {
                uint32_t b00 = f2tf(br[le][nt * 4 + 0]), b01 = f2tf(br[le][nt * 4 + 1]);
                uint32_t b10 = f2tf(br[le][nt * 4 + 2]), b11 = f2tf(br[le][nt * 4 + 3]);
#pragma unroll
                for (int mt = 0; mt < 2; mt++) {
                    float c4[4] = {0.f, 0.f, 0.f, 0.f};
                    mma8(c4, fa[le][mt][0], b00, b01);
                    mma8(c4, fa[le][mt][1], b10, b11);
                    int sA = nt * 8 + 2 * tg, ciA = mt * 16 + g;
                    tp[sA * 36 + ciA]           = f2tf_f(c4[0]);
                    tp[(sA + 1) * 36 + ciA]     = f2tf_f(c4[1]);
                    tp[sA * 36 + ciA + 8]       = f2tf_f(c4[2]);
                    tp[(sA + 1) * 36 + ciA + 8] = f2tf_f(c4[3]);
                }
            }
        }

#pragma unroll
        for (int c = 0; c < 2; c++) {
            // ---- GEMM1: RW[co=c*16+wid][ci][e], A-fragments via 4 coalesced
            //      LDG.128 per mt from the fragment-contiguous g_w3p ----
            const float* wb = g_w3p + (((size_t)(f * 2 + c) * 16 + wid) * 2) * 512;
            float* Rw = sm + RW_OFF + c * RWSZ + wid * 36;
#pragma unroll
            for (int mt = 0; mt < 2; mt++) {
                const float4* W4 = reinterpret_cast<const float4*>(wb + mt * 512);
                uint32_t ar[16];
#pragma unroll
                for (int q = 0; q < 4; q++) {
                    float4 v = __ldg(&W4[q * 32 + lane]);
                    ar[q * 4 + 0] = __float_as_uint(v.x);
                    ar[q * 4 + 1] = __float_as_uint(v.y);
                    ar[q * 4 + 2] = __float_as_uint(v.z);
                    ar[q * 4 + 3] = __float_as_uint(v.w);
                }
#pragma unroll
                for (int nt = 0; nt < 4; nt++) {
                    float c4[4] = {0.f, 0.f, 0.f, 0.f};
#pragma unroll
                    for (int k = 0; k < 4; k++)
                        mma8(c4, &ar[k * 4], hB[k][nt][0], hB[k][nt][1]);
                    int eb = nt * 8 + 2 * tg;
                    Rw[eb * 580 + mt * 16 + g]           = f2tf_f(c4[0]);
                    Rw[(eb + 1) * 580 + mt * 16 + g]     = f2tf_f(c4[1]);
                    Rw[eb * 580 + mt * 16 + g + 8]       = f2tf_f(c4[2]);
                    Rw[(eb + 1) * 580 + mt * 16 + g + 8] = f2tf_f(c4[3]);
                }
            }
            __syncthreads();

            // ---- GEMM3: out_e[co16,s16] += RW_e[co16,ci32] @ tmp_e[ci32,s16] ----
#pragma unroll
            for (int le = 0; le < 2; le++) {
                int e = wid * 2 + le;
                const float* R = sm + RW_OFF + c * RWSZ + e * 580;
                const float* T = sm + TMP_OFF + e * 580;
#pragma unroll
                for (int k = 0; k < 4; k++) {
                    uint32_t aa[4];
                    aa[0] = __float_as_uint(R[g * 36 + k * 8 + tg]);
                    aa[1] = __float_as_uint(R[(g + 8) * 36 + k * 8 + tg]);
                    aa[2] = __float_as_uint(R[g * 36 + k * 8 + tg + 4]);
                    aa[3] = __float_as_uint(R[(g + 8) * 36 + k * 8 + tg + 4]);
#pragma unroll
                    for (int nt = 0; nt < 2; nt++) {
                        uint32_t b0 = __float_as_uint(T[(nt * 8 + g) * 36 + k * 8 + tg]);
                        uint32_t b1 = __float_as_uint(T[(nt * 8 + g) * 36 + k * 8 + tg + 4]);
                        mma8(acc[le][c][nt], aa, b0, b1);
                    }
                }
            }
        }
    }

    // ---- BARRIER: all warps must finish their final GEMM3 TMP/RW reads before
    //      the epilogue scratch (stride 516, overlapping other warps' TMP rows)
    //      is written. ----
    __syncthreads();

    // ---- epilogue: acc -> smem scratch [e][co*16+s] (stride 516) -> coalesced gmem ----
#pragma unroll
    for (int le = 0; le < 2; le++) {
        float* o = sm + (wid * 2 + le) * 516;
#pragma unroll
        for (int c = 0; c < 2; c++)
#pragma unroll
            for (int nt = 0; nt < 2; nt++) {
                int co = c * 16 + g, s = nt * 8 + 2 * tg;
                o[co * 16 + s]           = acc[le][c][nt][0];
                o[co * 16 + s + 1]       = acc[le][c][nt][1];
                o[(co + 8) * 16 + s]     = acc[le][c][nt][2];
                o[(co + 8) * 16 + s + 1] = acc[le][c][nt][3];
            }
    }
    __syncthreads();
    {
        float4* dst = reinterpret_cast<float4*>(out + (size_t)e0 * 512);
#pragma unroll
        for (int j = 0; j < 8; j++) {
            int idx = t + j * 512;
            int e = idx >> 7, pos = (idx & 127) * 4;
            const float* s4 = sm + e * 516 + pos;
            dst[idx] = make_float4(s4[0], s4[1], s4[2], s4[3]);
        }
    }
}

// ---------------------------------------------------------------------------
// launch
// ---------------------------------------------------------------------------
extern "C" void kernel_launch(void* const* d_in, const int* in_sizes, int n_in,
                              void* d_out, int out_size) {
    (void)in_sizes; (void)n_in; (void)out_size;
    const float* features = (const float*)d_in[0];
    const float* edge     = (const float*)d_in[1];
    const float* basis    = (const float*)d_in[2];
    const float* w1  = (const float*)d_in[3];
    const float* b1  = (const float*)d_in[4];
    const float* g1  = (const float*)d_in[5];
    const float* be1 = (const float*)d_in[6];
    const float* w2  = (const float*)d_in[7];
    const float* b2  = (const float*)d_in[8];
    const float* g2  = (const float*)d_in[9];
    const float* be2 = (const float*)d_in[10];
    const float* w3  = (const float*)d_in[11];
    float* out = (float*)d_out;

    cudaFuncSetAttribute(conv_kernel, cudaFuncAttributeMaxDynamicSharedMemorySize, SMEM_BYTES);

    w3p_kernel<<<45056 * 32 / 256, 256>>>(w3);
    mlp_kernel<<<NE / 256, 256>>>(edge, w1, b1, g1, be1, w2, b2, g2, be2);
    conv_kernel<<<NE / 32, 512, SMEM_BYTES>>>(features, basis, out);
}